// round 9
// baseline (speedup 1.0000x reference)
#include <cuda_runtime.h>
#include <cstdint>
#include <cstddef>

#define NN 32768
#define EE 262144

static const size_t O_OUT_V = (size_t)NN * 64;
static const size_t O_SC_S  = (size_t)NN * 256;
static const size_t O_SC_V  = (size_t)NN * 320;

typedef unsigned long long ull;

// ---------------- device scratch ----------------
__device__ float4 g_xq[(size_t)NN * 64];     // input pack: (xv0,xv1,xv2,xs)
__device__ float4 g_xq2[(size_t)NN * 64];    // self-mixed: (v0,v1,v2,s)
__device__ float  g_tpw[(size_t)EE * 320];
__device__ ull    g_wsv[640 * 64];           // packed (W_sc_s, W_sc_v)
__device__ float2 g_wself[64 * 64];          // packed (W_self_s, W_self_v)
__device__ ull    g_wms2[64 * 64];           // paired (Wms[2k][d], Wms[2k+1][d])
__device__ ull    g_wmv2[96 * 64];           // paired (Wmv[2k][d], Wmv[2k+1][d])
__device__ int    g_cnt[NN];
__device__ int    g_off[NN + 1];
__device__ int    g_woff[NN];
__device__ int    g_eord[EE];
__device__ int    g_bsum[32];
__device__ int    g_bpre[32];

// ---------------- helpers ----------------
__device__ __forceinline__ ull pk2(float lo, float hi) {
    ull r; asm("mov.b64 %0, {%1, %2};" : "=l"(r) : "f"(lo), "f"(hi)); return r;
}
__device__ __forceinline__ void upk2(ull v, float& lo, float& hi) {
    asm("mov.b64 {%0, %1}, %2;" : "=f"(lo), "=f"(hi) : "l"(v));
}
__device__ __forceinline__ ull ff2(ull a, ull b, ull c) {
    ull d; asm("fma.rn.f32x2 %0, %1, %2, %3;" : "=l"(d) : "l"(a), "l"(b), "l"(c));
    return d;
}
__device__ __forceinline__ float fold2(ull v) {
    float lo, hi; upk2(v, lo, hi); return lo + hi;
}
__device__ __forceinline__ float silu_f(float x) {
    return x * __fdividef(1.0f, 1.0f + __expf(-x));
}

// ============================================================================
// K_prep: pack weights; zero counters
// ============================================================================
__global__ void k_prep(const float* __restrict__ Wscs, const float* __restrict__ Wscv,
                       const float* __restrict__ Wss,  const float* __restrict__ Wsv,
                       const float* __restrict__ Wms,  const float* __restrict__ Wmv) {
    const int i = blockIdx.x * 256 + threadIdx.x;
    if (i < 640 * 64) g_wsv[i] = pk2(Wscs[i], Wscv[i]);
    if (i < 64 * 64)  g_wself[i] = make_float2(Wss[i], Wsv[i]);
    if (i < 64 * 64) {
        const int kp = i >> 6, d = i & 63;
        g_wms2[i] = pk2(Wms[(2 * kp) * 64 + d], Wms[(2 * kp + 1) * 64 + d]);
    }
    if (i < 96 * 64) {
        const int kp = i >> 6, d = i & 63;
        g_wmv2[i] = pk2(Wmv[(2 * kp) * 64 + d], Wmv[(2 * kp + 1) * 64 + d]);
    }
    if (i < NN) g_cnt[i] = 0;
}

// K_prepx: pack (x_v, x_s) into float4; fused receiver histogram
__global__ void k_prepx(const float* __restrict__ xs_in,
                        const float* __restrict__ xv_in,
                        const int* __restrict__ recv) {
    const size_t i = (size_t)blockIdx.x * 256 + threadIdx.x;  // over N*C
    const float xs = xs_in[i];
    const float* p = xv_in + i * 3;
    g_xq[i] = make_float4(p[0], p[1], p[2], xs);
    if (i < EE) atomicAdd(&g_cnt[recv[i]], 1);
}

// ============================================================================
// K2 v6: edge MLP; hT[k][e] swizzled in smem; weights streamed from L2;
// 256 threads/block, 128 edges/block; thread tile = 4 edges x 8 outputs;
// 2 blocks/SM (16 warps).
// ============================================================================
#define HPITCH 128

__device__ __forceinline__ void mlp_zero4(ull acc[4][4]) {
#pragma unroll
    for (int j = 0; j < 4; j++)
#pragma unroll
        for (int q = 0; q < 4; q++) acc[j][q] = 0ull;
}

__device__ __forceinline__ void mac4(
    ull acc[4][4], const float4 ha,
    const ulonglong2 wa, const ulonglong2 wb)
{
    const float hv[4] = {ha.x, ha.y, ha.z, ha.w};
#pragma unroll
    for (int j = 0; j < 4; j++) {
        const ull p = pk2(hv[j], hv[j]);
        acc[j][0] = ff2(p, wa.x, acc[j][0]);
        acc[j][1] = ff2(p, wa.y, acc[j][1]);
        acc[j][2] = ff2(p, wb.x, acc[j][2]);
        acc[j][3] = ff2(p, wb.y, acc[j][3]);
    }
}

// 64-K chunk; h from smem (swizzled), weights streamed from global.
template <int WSTRIDE>
__device__ __forceinline__ void chunk64_g(
    const float* __restrict__ hSrc, const float* __restrict__ W,
    const int e0, const int og, ull acc[4][4])
{
    const float* wp = W + og * 8;
#pragma unroll 1
    for (int k8 = 0; k8 < 8; k8++) {
        const int cofs = e0 ^ (k8 << 4);
        const float* hp = hSrc + k8 * 8 * HPITCH + cofs;
        const float* wk = wp + k8 * 8 * WSTRIDE;
#pragma unroll
        for (int kk = 0; kk < 8; kk++) {
            const float4 ha = *(const float4*)(hp + kk * HPITCH);
            const ulonglong2 wa = __ldg((const ulonglong2*)(wk + kk * WSTRIDE));
            const ulonglong2 wb = __ldg((const ulonglong2*)(wk + kk * WSTRIDE + 4));
            mac4(acc, ha, wa, wb);
        }
    }
}

// store 8 outputs x 4 edges into hT with silu
__device__ __forceinline__ void store_h4(
    ull acc[4][4], float* __restrict__ hDst,
    const int e0, const int og, const float scale)
{
#pragma unroll
    for (int q = 0; q < 4; q++) {
        float l[4], h[4];
#pragma unroll
        for (int j = 0; j < 4; j++) upk2(acc[j][q], l[j], h[j]);
        const int k0 = og * 8 + 2 * q;    // k0>>3 == og
        const int k1 = k0 + 1;
        const int c0 = e0 ^ (og << 4);
        *(float4*)(hDst + k0 * HPITCH + c0) =
            make_float4(silu_f(l[0] * scale), silu_f(l[1] * scale),
                        silu_f(l[2] * scale), silu_f(l[3] * scale));
        *(float4*)(hDst + k1 * HPITCH + c0) =
            make_float4(silu_f(h[0] * scale), silu_f(h[1] * scale),
                        silu_f(h[2] * scale), silu_f(h[3] * scale));
    }
}

__global__ __launch_bounds__(256, 2) void k_mlp(
    const float* __restrict__ feats,
    const float* __restrict__ W0, const float* __restrict__ W1,
    const float* __restrict__ W2, const float* __restrict__ W3)
{
    extern __shared__ float sw[];
    float* sW0 = sw;             // [8][64]
    float* hA  = sw + 512;       // [64][128] transposed
    float* hB  = sw + 8704;      // [64][128] transposed

    const int t = threadIdx.x;
    for (int i = t; i < 512; i += 256) sW0[i] = W0[i];

    // stage feats -> hA[k][e] (k<8 -> no swizzle)
    const size_t fbase = (size_t)blockIdx.x * 128 * 8;
    for (int i = t; i < 1024; i += 256)
        hA[(i & 7) * HPITCH + (i >> 3)] = feats[fbase + i];
    __syncthreads();

    const int og = t & 7;        // outputs og*8 .. +7
    const int e0 = (t >> 3) * 4; // edges e0 .. e0+3

    ull acc[4][4];

    // layer 0: K=8, scale 1/sqrt(8), silu -> hB
    {
        mlp_zero4(acc);
        const float* wp = sW0 + og * 8;
#pragma unroll
        for (int k = 0; k < 8; k++) {
            const float4 ha = *(const float4*)(hA + k * HPITCH + e0);
            const ulonglong2 wa = *(const ulonglong2*)(wp + k * 64);
            const ulonglong2 wb = *(const ulonglong2*)(wp + k * 64 + 4);
            mac4(acc, ha, wa, wb);
        }
        store_h4(acc, hB, e0, og, 0.3535533905932738f);
    }
    __syncthreads();

    // layer 1: hB -> hA  (W1 streamed from L2)
    mlp_zero4(acc);
    chunk64_g<64>(hB, W1, e0, og, acc);
    store_h4(acc, hA, e0, og, 0.125f);
    __syncthreads();

    // layer 2: hA -> hB  (W2 streamed from L2)
    mlp_zero4(acc);
    chunk64_g<64>(hA, W2, e0, og, acc);
    store_h4(acc, hB, e0, og, 0.125f);
    __syncthreads();

    // layer 3: hB -> g_tpw, 5 chunks of 64 outputs (W3 streamed from L2)
    const size_t tbase = (size_t)blockIdx.x * 128;
#pragma unroll 1
    for (int ch = 0; ch < 5; ch++) {
        mlp_zero4(acc);
        chunk64_g<320>(hB, W3 + ch * 64, e0, og, acc);
#pragma unroll
        for (int j = 0; j < 4; j++) {
            float l0, h0, l1, h1, l2, h2, l3, h3;
            upk2(acc[j][0], l0, h0); upk2(acc[j][1], l1, h1);
            upk2(acc[j][2], l2, h2); upk2(acc[j][3], l3, h3);
            float* op = g_tpw + (tbase + e0 + j) * 320 + ch * 64 + og * 8;
            *(float4*)op =
                make_float4(l0 * 0.125f, h0 * 0.125f, l1 * 0.125f, h1 * 0.125f);
            *(float4*)(op + 4) =
                make_float4(l2 * 0.125f, h2 * 0.125f, l3 * 0.125f, h3 * 0.125f);
        }
    }
}

// ============================================================================
// CSR build: hierarchical scan -> fill -> sort (count fused into k_prepx)
// ============================================================================
__global__ void k_scan_a() {      // grid 32, block 1024
    __shared__ int ss[1024];
    const int t = threadIdx.x;
    const int i = blockIdx.x * 1024 + t;
    const int v = g_cnt[i];
    ss[t] = v;
    __syncthreads();
    for (int dd = 1; dd < 1024; dd <<= 1) {
        const int u = (t >= dd) ? ss[t - dd] : 0;
        __syncthreads();
        ss[t] += u;
        __syncthreads();
    }
    g_off[i] = ss[t] - v;
    g_woff[i] = 0;
    if (t == 1023) g_bsum[blockIdx.x] = ss[t];
}
__global__ void k_scan_b() {      // 1 block, 32 threads
    const int t = threadIdx.x;
    const int orig = g_bsum[t];
    int v = orig;
    for (int dd = 1; dd < 32; dd <<= 1) {
        const int u = __shfl_up_sync(0xffffffffu, v, dd);
        if (t >= dd) v += u;
    }
    g_bpre[t] = v - orig;
    if (t == 31) g_off[NN] = v;
}
__global__ void k_scan_c() {      // grid 128 x 256
    const int i = blockIdx.x * 256 + threadIdx.x;
    g_off[i] += g_bpre[i >> 10];
}
__global__ void k_fill(const int* __restrict__ recv) {
    const int e = blockIdx.x * blockDim.x + threadIdx.x;
    if (e < EE) {
        const int r = recv[e];
        const int p = atomicAdd(&g_woff[r], 1);
        g_eord[g_off[r] + p] = e;
    }
}
__global__ void k_sort() {
    const int n = blockIdx.x * blockDim.x + threadIdx.x;
    if (n >= NN) return;
    const int s = g_off[n], e = g_off[n + 1];
    for (int i = s + 1; i < e; i++) {
        const int v = g_eord[i];
        int j = i - 1;
        while (j >= s && g_eord[j] > v) { g_eord[j + 1] = g_eord[j]; j--; }
        g_eord[j + 1] = v;
    }
}

// ============================================================================
// K1: per-node sc_s/sc_v + self-mix, weights smem-stationary, d-quartered.
// grid (128, 4) x 256 threads; dyn smem 90112 B
// ============================================================================
__global__ __launch_bounds__(256, 2) void k_node(
    const float* __restrict__ attr, float* __restrict__ out)
{
    extern __shared__ ull dynsm[];
    ull*    swsv   = dynsm;                        // [c*160 + a*16 + d]
    float2* swself = (float2*)(dynsm + 640 * 16);  // [c*16 + d]

    const int t = threadIdx.x;
    const int dq = blockIdx.y;
    const int dd = dq * 16;

    for (int i = t; i < 640 * 16; i += 256) {
        const int ca = i >> 4, d_ = i & 15;
        swsv[i] = g_wsv[ca * 64 + dd + d_];
    }
    for (int i = t; i < 64 * 16; i += 256) {
        const int c = i >> 4, d_ = i & 15;
        swself[i] = g_wself[c * 64 + dd + d_];
    }
    __syncthreads();

    const int d = t & 15, grp = t >> 4;
    const int nbase = blockIdx.x * 256 + grp * 16;
    const int D = dd + d;
    const float S640 = 0.039528470752104741f;  // 1/sqrt(640)

    for (int pass = 0; pass < 8; pass++) {
        const int nA = nbase + pass * 2;
        const int nB = nA + 1;

        ull aPA[10], aPB[10];
#pragma unroll
        for (int a = 0; a < 10; a++) {
            const float vA = __ldg(attr + (size_t)nA * 10 + a);
            const float vB = __ldg(attr + (size_t)nB * 10 + a);
            aPA[a] = pk2(vA, vA);
            aPB[a] = pk2(vB, vB);
        }

        float accS[2]  = {0.f, 0.f}, accS2[2] = {0.f, 0.f};
        float aV2[2]   = {0.f, 0.f}, aV2s[2]  = {0.f, 0.f};
        ull   aV01[2]  = {0ull, 0ull}, aV01s[2] = {0ull, 0ull};

        const float4* xqA = g_xq + (size_t)nA * 64;
        const float4* xqB = g_xq + (size_t)nB * 64;

#pragma unroll 2
        for (int c = 0; c < 64; c++) {
            const float4 xA = __ldg(xqA + c);
            const float4 xB = __ldg(xqB + c);
            const float2 wsf = swself[c * 16 + d];
            const ull wvd = pk2(wsf.y, wsf.y);

            accS2[0]  = fmaf(xA.w, wsf.x, accS2[0]);
            aV01s[0]  = ff2(pk2(xA.x, xA.y), wvd, aV01s[0]);
            aV2s[0]   = fmaf(xA.z, wsf.y, aV2s[0]);
            accS2[1]  = fmaf(xB.w, wsf.x, accS2[1]);
            aV01s[1]  = ff2(pk2(xB.x, xB.y), wvd, aV01s[1]);
            aV2s[1]   = fmaf(xB.z, wsf.y, aV2s[1]);

            ull mA = 0ull, mB = 0ull;
            const ull* wp = swsv + c * 160 + d;
#pragma unroll
            for (int a = 0; a < 10; a++) {
                const ull w = wp[a * 16];
                mA = ff2(aPA[a], w, mA);
                mB = ff2(aPB[a], w, mB);
            }
            float MsA, MvA, MsB, MvB;
            upk2(mA, MsA, MvA);
            upk2(mB, MsB, MvB);

            accS[0] = fmaf(xA.w, MsA, accS[0]);
            aV01[0] = ff2(pk2(xA.x, xA.y), pk2(MvA, MvA), aV01[0]);
            aV2[0]  = fmaf(xA.z, MvA, aV2[0]);
            accS[1] = fmaf(xB.w, MsB, accS[1]);
            aV01[1] = ff2(pk2(xB.x, xB.y), pk2(MvB, MvB), aV01[1]);
            aV2[1]  = fmaf(xB.z, MvB, aV2[1]);
        }

#pragma unroll
        for (int j = 0; j < 2; j++) {
            const int n = nA + j;
            out[O_SC_S + (size_t)n * 64 + D] = accS[j] * S640;
            float v0, v1; upk2(aV01[j], v0, v1);
            const size_t vb = O_SC_V + (size_t)n * 192 + (size_t)D * 3;
            out[vb]     = v0 * S640;
            out[vb + 1] = v1 * S640;
            out[vb + 2] = aV2[j] * S640;
            float s0, s1; upk2(aV01s[j], s0, s1);
            g_xq2[(size_t)n * 64 + D] =
                make_float4(s0 * 0.125f, s1 * 0.125f, aV2s[j] * 0.125f,
                            accS2[j] * 0.125f);
        }
    }
}

// ============================================================================
// K4 v3: gather aggregation + output GEMMs with weights amortized over the
// 4 node-groups (threads 0-63: out_s x4; threads 64-255: out_v (d,comp) x4).
// ============================================================================
__global__ __launch_bounds__(256) void k_agg(
    const int* __restrict__ send, const float* __restrict__ eattr,
    float* __restrict__ out)
{
    __shared__ __align__(16) float sms[4][128];
    __shared__ __align__(16) float sv0[4][192];
    __shared__ __align__(16) float sv1[4][192];
    __shared__ __align__(16) float sv2[4][192];

    const int t = threadIdx.x;
    const int g = t >> 6, c = t & 63;
    const int nb = blockIdx.x * 4;
    const int n = nb + g;
    const int e0 = g_off[n], e1 = g_off[n + 1];

    float as0 = 0.f, as1 = 0.f;
    ull   av0_01 = 0ull, av1_01 = 0ull, av2_01 = 0ull;
    float av0_2 = 0.f, av1_2 = 0.f, av2_2 = 0.f;

    for (int p = e0; p < e1; p++) {
        const int e = g_eord[p];
        const int s = __ldg(send + e);
        const float4 ea = __ldg((const float4*)eattr + e);
        const float sh0 = ea.x, s1x = ea.y, s1y = ea.z, s1z = ea.w;
        const float* tp = g_tpw + (size_t)e * 320 + c;
        const float w0 = tp[0], w1 = tp[64], w2 = tp[128], w3 = tp[192], w4 = tp[256];
        const float4 xq = __ldg(g_xq2 + (size_t)s * 64 + c);
        const float xs = xq.w;

        as0 = fmaf(w0 * xs, sh0, as0);
        const float dt = xq.x * s1x + xq.y * s1y + xq.z * s1z;
        as1 = fmaf(w3, dt, as1);

        const float t1 = w1 * xs;
        av0_01 = ff2(pk2(t1, t1), pk2(s1x, s1y), av0_01);
        av0_2  = fmaf(t1, s1z, av0_2);

        const float w2sh = w2 * sh0;
        av1_01 = ff2(pk2(xq.x, xq.y), pk2(w2sh, w2sh), av1_01);
        av1_2  = fmaf(w2sh, xq.z, av1_2);

        const float cx = xq.y * s1z - xq.z * s1y;
        const float cy = xq.z * s1x - xq.x * s1z;
        const float cz = xq.x * s1y - xq.y * s1x;
        av2_01 = ff2(pk2(cx, cy), pk2(w4, w4), av2_01);
        av2_2  = fmaf(w4, cz, av2_2);
    }

    const float INV  = 0.3535533905932738f;            // 1/sqrt(8)
    const float INV3 = INV * 0.5773502691896258f;
    const float INV2 = INV * 0.7071067811865476f;
    sms[g][c]      = as0 * INV;
    sms[g][64 + c] = as1 * INV3;
    {
        float a, b;
        upk2(av0_01, a, b);
        sv0[g][c] = a * INV;  sv1[g][c] = b * INV;  sv2[g][c] = av0_2 * INV;
        upk2(av1_01, a, b);
        sv0[g][64 + c] = a * INV;  sv1[g][64 + c] = b * INV;
        sv2[g][64 + c] = av1_2 * INV;
        upk2(av2_01, a, b);
        sv0[g][128 + c] = a * INV2;  sv1[g][128 + c] = b * INV2;
        sv2[g][128 + c] = av2_2 * INV2;
    }
    __syncthreads();

    if (t < 64) {
        // out_s for all 4 nodes: one weight load serves 4 dot products
        const int d = t;
        ull os[4] = {0ull, 0ull, 0ull, 0ull};
#pragma unroll 4
        for (int kp = 0; kp < 64; kp++) {
            const ull w = __ldg(g_wms2 + kp * 64 + d);
#pragma unroll
            for (int q = 0; q < 4; q++)
                os[q] = ff2(((const ull*)sms[q])[kp], w, os[q]);
        }
#pragma unroll
        for (int q = 0; q < 4; q++)
            out[(size_t)(nb + q) * 64 + d] = fold2(os[q]) * 0.08838834764831845f;
    } else {
        // out_v: thread = (d, comp); one weight load serves 4 nodes
        const int u = t - 64;
        const int d = u & 63;
        const int comp = u >> 6;  // 0,1,2
        const float* pl = (comp == 0) ? &sv0[0][0]
                        : (comp == 1) ? &sv1[0][0] : &sv2[0][0];
        ull ov[4] = {0ull, 0ull, 0ull, 0ull};
#pragma unroll 4
        for (int kp = 0; kp < 96; kp++) {
            const ull w = __ldg(g_wmv2 + kp * 64 + d);
#pragma unroll
            for (int q = 0; q < 4; q++)
                ov[q] = ff2(((const ull*)(pl + q * 192))[kp], w, ov[q]);
        }
        const float S192 = 0.07216878364870323f;  // 1/sqrt(192)
#pragma unroll
        for (int q = 0; q < 4; q++)
            out[O_OUT_V + (size_t)(nb + q) * 192 + (size_t)d * 3 + comp] =
                fold2(ov[q]) * S192;
    }
}

// ============================================================================
extern "C" void kernel_launch(void* const* d_in, const int* in_sizes, int n_in,
                              void* d_out, int out_size)
{
    const float* node_attrs = (const float*)d_in[0];
    const float* x_s        = (const float*)d_in[1];
    const float* x_v        = (const float*)d_in[2];
    const float* edge_attrs = (const float*)d_in[3];
    const float* edge_feats = (const float*)d_in[4];
    const int*   senders    = (const int*)d_in[5];
    const int*   receivers  = (const int*)d_in[6];
    const float* W_sc_s     = (const float*)d_in[7];
    const float* W_sc_v     = (const float*)d_in[8];
    const float* W_self_s   = (const float*)d_in[9];
    const float* W_self_v   = (const float*)d_in[10];
    const float* mlp_W0     = (const float*)d_in[11];
    const float* mlp_W1     = (const float*)d_in[12];
    const float* mlp_W2     = (const float*)d_in[13];
    const float* mlp_W3     = (const float*)d_in[14];
    const float* W_msg_s    = (const float*)d_in[15];
    const float* W_msg_v    = (const float*)d_in[16];
    float* out = (float*)d_out;

    const size_t mlp_smem  = (size_t)(512 + 2 * 64 * HPITCH) * sizeof(float); // 67584
    const size_t node_smem = (size_t)(640 * 16) * 8 + (size_t)(64 * 16) * 8;
    cudaFuncSetAttribute(k_mlp, cudaFuncAttributeMaxDynamicSharedMemorySize,
                         (int)mlp_smem);
    cudaFuncSetAttribute(k_node, cudaFuncAttributeMaxDynamicSharedMemorySize,
                         (int)node_smem);

    k_prep<<<160, 256>>>(W_sc_s, W_sc_v, W_self_s, W_self_v, W_msg_s, W_msg_v);
    k_prepx<<<NN * 64 / 256, 256>>>(x_s, x_v, receivers);
    k_mlp<<<EE / 128, 256, mlp_smem>>>(edge_feats, mlp_W0, mlp_W1, mlp_W2, mlp_W3);
    k_scan_a<<<32, 1024>>>();
    k_scan_b<<<1, 32>>>();
    k_scan_c<<<128, 256>>>();
    k_fill<<<EE / 256, 256>>>(receivers);
    k_sort<<<NN / 128, 128>>>();
    k_node<<<dim3(128, 4), 256, node_smem>>>(node_attrs, out);
    k_agg<<<NN / 4, 256>>>(senders, edge_attrs, out);
}

// round 10
// speedup vs baseline: 1.1899x; 1.1899x over previous
#include <cuda_runtime.h>
#include <cstdint>
#include <cstddef>

#define NN 32768
#define EE 262144

static const size_t O_OUT_V = (size_t)NN * 64;
static const size_t O_SC_S  = (size_t)NN * 256;
static const size_t O_SC_V  = (size_t)NN * 320;

typedef unsigned long long ull;

// ---------------- device scratch ----------------
__device__ float4 g_xq[(size_t)NN * 64];     // input pack: (xv0,xv1,xv2,xs)
__device__ float4 g_xq2[(size_t)NN * 64];    // self-mixed: (v0,v1,v2,s)
__device__ float  g_tpw[(size_t)EE * 320];
__device__ ull    g_wsv[640 * 64];           // packed (W_sc_s, W_sc_v)
__device__ float2 g_wself[64 * 64];          // packed (W_self_s, W_self_v)
__device__ ull    g_wms2[64 * 64];           // paired (Wms[2k][d], Wms[2k+1][d])
__device__ ull    g_wmv2[96 * 64];           // paired (Wmv[2k][d], Wmv[2k+1][d])
__device__ int    g_cnt[NN];
__device__ int    g_off[NN + 1];
__device__ int    g_woff[NN];
__device__ int    g_eord[EE];
__device__ int    g_bsum[32];
__device__ int    g_bpre[32];

// ---------------- helpers ----------------
__device__ __forceinline__ ull pk2(float lo, float hi) {
    ull r; asm("mov.b64 %0, {%1, %2};" : "=l"(r) : "f"(lo), "f"(hi)); return r;
}
__device__ __forceinline__ void upk2(ull v, float& lo, float& hi) {
    asm("mov.b64 {%0, %1}, %2;" : "=f"(lo), "=f"(hi) : "l"(v));
}
__device__ __forceinline__ ull ff2(ull a, ull b, ull c) {
    ull d; asm("fma.rn.f32x2 %0, %1, %2, %3;" : "=l"(d) : "l"(a), "l"(b), "l"(c));
    return d;
}
__device__ __forceinline__ float fold2(ull v) {
    float lo, hi; upk2(v, lo, hi); return lo + hi;
}
__device__ __forceinline__ float silu_f(float x) {
    return x * __fdividef(1.0f, 1.0f + __expf(-x));
}

// ============================================================================
// K_prep: pack weights; zero counters
// ============================================================================
__global__ void k_prep(const float* __restrict__ Wscs, const float* __restrict__ Wscv,
                       const float* __restrict__ Wss,  const float* __restrict__ Wsv,
                       const float* __restrict__ Wms,  const float* __restrict__ Wmv) {
    const int i = blockIdx.x * 256 + threadIdx.x;
    if (i < 640 * 64) g_wsv[i] = pk2(Wscs[i], Wscv[i]);
    if (i < 64 * 64)  g_wself[i] = make_float2(Wss[i], Wsv[i]);
    if (i < 64 * 64) {
        const int kp = i >> 6, d = i & 63;
        g_wms2[i] = pk2(Wms[(2 * kp) * 64 + d], Wms[(2 * kp + 1) * 64 + d]);
    }
    if (i < 96 * 64) {
        const int kp = i >> 6, d = i & 63;
        g_wmv2[i] = pk2(Wmv[(2 * kp) * 64 + d], Wmv[(2 * kp + 1) * 64 + d]);
    }
    if (i < NN) g_cnt[i] = 0;
}

// K_prepx: pack (x_v, x_s) into float4; fused receiver histogram
__global__ void k_prepx(const float* __restrict__ xs_in,
                        const float* __restrict__ xv_in,
                        const int* __restrict__ recv) {
    const size_t i = (size_t)blockIdx.x * 256 + threadIdx.x;  // over N*C
    const float xs = xs_in[i];
    const float* p = xv_in + i * 3;
    g_xq[i] = make_float4(p[0], p[1], p[2], xs);
    if (i < EE) atomicAdd(&g_cnt[recv[i]], 1);
}

// ============================================================================
// K2 (R8 config): edge MLP; hT[k][e] swizzled in smem; weights streamed from
// L2 via LDG; 128 threads/block, 128 edges/block; tile = 8 edges x 8 outputs;
// smem = 67584 B -> 3 blocks/SM (12 warps).
// ============================================================================
#define HPITCH 128

__device__ __forceinline__ void mlp_zero8(ull acc[8][4]) {
#pragma unroll
    for (int j = 0; j < 8; j++)
#pragma unroll
        for (int q = 0; q < 4; q++) acc[j][q] = 0ull;
}

__device__ __forceinline__ void mac8(
    ull acc[8][4], const float4 ha, const float4 hb,
    const ulonglong2 wa, const ulonglong2 wb)
{
    const float hv[8] = {ha.x, ha.y, ha.z, ha.w, hb.x, hb.y, hb.z, hb.w};
#pragma unroll
    for (int j = 0; j < 8; j++) {
        const ull p = pk2(hv[j], hv[j]);
        acc[j][0] = ff2(p, wa.x, acc[j][0]);
        acc[j][1] = ff2(p, wa.y, acc[j][1]);
        acc[j][2] = ff2(p, wb.x, acc[j][2]);
        acc[j][3] = ff2(p, wb.y, acc[j][3]);
    }
}

template <int WSTRIDE>
__device__ __forceinline__ void chunk64_g(
    const float* __restrict__ hSrc, const float* __restrict__ W,
    const int e0, const int og, ull acc[8][4])
{
    const float* wp = W + og * 8;
#pragma unroll 1
    for (int k8 = 0; k8 < 8; k8++) {
        const int cofs = e0 ^ (k8 << 4);
        const float* hp = hSrc + k8 * 8 * HPITCH + cofs;
        const float* wk = wp + k8 * 8 * WSTRIDE;
#pragma unroll
        for (int kk = 0; kk < 8; kk++) {
            const float4 ha = *(const float4*)(hp + kk * HPITCH);
            const float4 hb = *(const float4*)(hp + kk * HPITCH + 4);
            const ulonglong2 wa = __ldg((const ulonglong2*)(wk + kk * WSTRIDE));
            const ulonglong2 wb = __ldg((const ulonglong2*)(wk + kk * WSTRIDE + 4));
            mac8(acc, ha, hb, wa, wb);
        }
    }
}

__device__ __forceinline__ void store_h8(
    ull acc[8][4], float* __restrict__ hDst,
    const int e0, const int og, const float scale)
{
#pragma unroll
    for (int q = 0; q < 4; q++) {
        float l[8], h[8];
#pragma unroll
        for (int j = 0; j < 8; j++) upk2(acc[j][q], l[j], h[j]);
        const int k0 = og * 8 + 2 * q;    // k0>>3 == og
        const int k1 = k0 + 1;
        const int c0 = e0 ^ (og << 4);
        float* r0 = hDst + k0 * HPITCH + c0;
        float* r1 = hDst + k1 * HPITCH + c0;
        *(float4*)r0 =
            make_float4(silu_f(l[0] * scale), silu_f(l[1] * scale),
                        silu_f(l[2] * scale), silu_f(l[3] * scale));
        *(float4*)(r0 + 4) =
            make_float4(silu_f(l[4] * scale), silu_f(l[5] * scale),
                        silu_f(l[6] * scale), silu_f(l[7] * scale));
        *(float4*)r1 =
            make_float4(silu_f(h[0] * scale), silu_f(h[1] * scale),
                        silu_f(h[2] * scale), silu_f(h[3] * scale));
        *(float4*)(r1 + 4) =
            make_float4(silu_f(h[4] * scale), silu_f(h[5] * scale),
                        silu_f(h[6] * scale), silu_f(h[7] * scale));
    }
}

__global__ __launch_bounds__(128, 3) void k_mlp(
    const float* __restrict__ feats,
    const float* __restrict__ W0, const float* __restrict__ W1,
    const float* __restrict__ W2, const float* __restrict__ W3)
{
    extern __shared__ float sw[];
    float* sW0 = sw;             // [8][64]
    float* hA  = sw + 512;       // [64][128] transposed
    float* hB  = sw + 8704;      // [64][128] transposed

    const int t = threadIdx.x;
    for (int i = t; i < 512; i += 128) sW0[i] = W0[i];

    const size_t fbase = (size_t)blockIdx.x * 128 * 8;
    for (int i = t; i < 1024; i += 128)
        hA[(i & 7) * HPITCH + (i >> 3)] = feats[fbase + i];
    __syncthreads();

    const int og = t & 7;        // outputs og*8 .. +7
    const int e0 = (t >> 3) * 8; // edges e0 .. e0+7

    ull acc[8][4];

    // layer 0: K=8, scale 1/sqrt(8), silu -> hB
    {
        mlp_zero8(acc);
        const float* wp = sW0 + og * 8;
#pragma unroll
        for (int k = 0; k < 8; k++) {
            const float4 ha = *(const float4*)(hA + k * HPITCH + e0);
            const float4 hb = *(const float4*)(hA + k * HPITCH + e0 + 4);
            const ulonglong2 wa = *(const ulonglong2*)(wp + k * 64);
            const ulonglong2 wb = *(const ulonglong2*)(wp + k * 64 + 4);
            mac8(acc, ha, hb, wa, wb);
        }
        store_h8(acc, hB, e0, og, 0.3535533905932738f);
    }
    __syncthreads();

    // layer 1: hB -> hA  (W1 streamed from L2)
    mlp_zero8(acc);
    chunk64_g<64>(hB, W1, e0, og, acc);
    store_h8(acc, hA, e0, og, 0.125f);
    __syncthreads();

    // layer 2: hA -> hB  (W2 streamed from L2)
    mlp_zero8(acc);
    chunk64_g<64>(hA, W2, e0, og, acc);
    store_h8(acc, hB, e0, og, 0.125f);
    __syncthreads();

    // layer 3: hB -> g_tpw, 5 chunks of 64 outputs (W3 streamed from L2)
    const size_t tbase = (size_t)blockIdx.x * 128;
#pragma unroll 1
    for (int ch = 0; ch < 5; ch++) {
        mlp_zero8(acc);
        chunk64_g<320>(hB, W3 + ch * 64, e0, og, acc);
#pragma unroll
        for (int j = 0; j < 8; j++) {
            float l0, h0, l1, h1, l2, h2, l3, h3;
            upk2(acc[j][0], l0, h0); upk2(acc[j][1], l1, h1);
            upk2(acc[j][2], l2, h2); upk2(acc[j][3], l3, h3);
            float* op = g_tpw + (tbase + e0 + j) * 320 + ch * 64 + og * 8;
            *(float4*)op =
                make_float4(l0 * 0.125f, h0 * 0.125f, l1 * 0.125f, h1 * 0.125f);
            *(float4*)(op + 4) =
                make_float4(l2 * 0.125f, h2 * 0.125f, l3 * 0.125f, h3 * 0.125f);
        }
    }
}

// ============================================================================
// CSR build: hierarchical scan -> fill -> sort (count fused into k_prepx)
// ============================================================================
__global__ void k_scan_a() {      // grid 32, block 1024
    __shared__ int ss[1024];
    const int t = threadIdx.x;
    const int i = blockIdx.x * 1024 + t;
    const int v = g_cnt[i];
    ss[t] = v;
    __syncthreads();
    for (int dd = 1; dd < 1024; dd <<= 1) {
        const int u = (t >= dd) ? ss[t - dd] : 0;
        __syncthreads();
        ss[t] += u;
        __syncthreads();
    }
    g_off[i] = ss[t] - v;
    g_woff[i] = 0;
    if (t == 1023) g_bsum[blockIdx.x] = ss[t];
}
__global__ void k_scan_b() {      // 1 block, 32 threads
    const int t = threadIdx.x;
    const int orig = g_bsum[t];
    int v = orig;
    for (int dd = 1; dd < 32; dd <<= 1) {
        const int u = __shfl_up_sync(0xffffffffu, v, dd);
        if (t >= dd) v += u;
    }
    g_bpre[t] = v - orig;
    if (t == 31) g_off[NN] = v;
}
__global__ void k_scan_c() {      // grid 128 x 256
    const int i = blockIdx.x * 256 + threadIdx.x;
    g_off[i] += g_bpre[i >> 10];
}
__global__ void k_fill(const int* __restrict__ recv) {
    const int e = blockIdx.x * blockDim.x + threadIdx.x;
    if (e < EE) {
        const int r = recv[e];
        const int p = atomicAdd(&g_woff[r], 1);
        g_eord[g_off[r] + p] = e;
    }
}
__global__ void k_sort() {
    const int n = blockIdx.x * blockDim.x + threadIdx.x;
    if (n >= NN) return;
    const int s = g_off[n], e = g_off[n + 1];
    for (int i = s + 1; i < e; i++) {
        const int v = g_eord[i];
        int j = i - 1;
        while (j >= s && g_eord[j] > v) { g_eord[j + 1] = g_eord[j]; j--; }
        g_eord[j + 1] = v;
    }
}

// ============================================================================
// K1: per-node sc_s/sc_v + self-mix, weights smem-stationary, d-quartered.
// grid (128, 4) x 256 threads; dyn smem 90112 B    [profiled slot #4]
// ============================================================================
__global__ __launch_bounds__(256, 2) void k_node(
    const float* __restrict__ attr, float* __restrict__ out)
{
    extern __shared__ ull dynsm[];
    ull*    swsv   = dynsm;                        // [c*160 + a*16 + d]
    float2* swself = (float2*)(dynsm + 640 * 16);  // [c*16 + d]

    const int t = threadIdx.x;
    const int dq = blockIdx.y;
    const int dd = dq * 16;

    for (int i = t; i < 640 * 16; i += 256) {
        const int ca = i >> 4, d_ = i & 15;
        swsv[i] = g_wsv[ca * 64 + dd + d_];
    }
    for (int i = t; i < 64 * 16; i += 256) {
        const int c = i >> 4, d_ = i & 15;
        swself[i] = g_wself[c * 64 + dd + d_];
    }
    __syncthreads();

    const int d = t & 15, grp = t >> 4;
    const int nbase = blockIdx.x * 256 + grp * 16;
    const int D = dd + d;
    const float S640 = 0.039528470752104741f;  // 1/sqrt(640)

    for (int pass = 0; pass < 8; pass++) {
        const int nA = nbase + pass * 2;
        const int nB = nA + 1;

        ull aPA[10], aPB[10];
#pragma unroll
        for (int a = 0; a < 10; a++) {
            const float vA = __ldg(attr + (size_t)nA * 10 + a);
            const float vB = __ldg(attr + (size_t)nB * 10 + a);
            aPA[a] = pk2(vA, vA);
            aPB[a] = pk2(vB, vB);
        }

        float accS[2]  = {0.f, 0.f}, accS2[2] = {0.f, 0.f};
        float aV2[2]   = {0.f, 0.f}, aV2s[2]  = {0.f, 0.f};
        ull   aV01[2]  = {0ull, 0ull}, aV01s[2] = {0ull, 0ull};

        const float4* xqA = g_xq + (size_t)nA * 64;
        const float4* xqB = g_xq + (size_t)nB * 64;

#pragma unroll 2
        for (int c = 0; c < 64; c++) {
            const float4 xA = __ldg(xqA + c);
            const float4 xB = __ldg(xqB + c);
            const float2 wsf = swself[c * 16 + d];
            const ull wvd = pk2(wsf.y, wsf.y);

            accS2[0]  = fmaf(xA.w, wsf.x, accS2[0]);
            aV01s[0]  = ff2(pk2(xA.x, xA.y), wvd, aV01s[0]);
            aV2s[0]   = fmaf(xA.z, wsf.y, aV2s[0]);
            accS2[1]  = fmaf(xB.w, wsf.x, accS2[1]);
            aV01s[1]  = ff2(pk2(xB.x, xB.y), wvd, aV01s[1]);
            aV2s[1]   = fmaf(xB.z, wsf.y, aV2s[1]);

            ull mA = 0ull, mB = 0ull;
            const ull* wp = swsv + c * 160 + d;
#pragma unroll
            for (int a = 0; a < 10; a++) {
                const ull w = wp[a * 16];
                mA = ff2(aPA[a], w, mA);
                mB = ff2(aPB[a], w, mB);
            }
            float MsA, MvA, MsB, MvB;
            upk2(mA, MsA, MvA);
            upk2(mB, MsB, MvB);

            accS[0] = fmaf(xA.w, MsA, accS[0]);
            aV01[0] = ff2(pk2(xA.x, xA.y), pk2(MvA, MvA), aV01[0]);
            aV2[0]  = fmaf(xA.z, MvA, aV2[0]);
            accS[1] = fmaf(xB.w, MsB, accS[1]);
            aV01[1] = ff2(pk2(xB.x, xB.y), pk2(MvB, MvB), aV01[1]);
            aV2[1]  = fmaf(xB.z, MvB, aV2[1]);
        }

#pragma unroll
        for (int j = 0; j < 2; j++) {
            const int n = nA + j;
            out[O_SC_S + (size_t)n * 64 + D] = accS[j] * S640;
            float v0, v1; upk2(aV01[j], v0, v1);
            const size_t vb = O_SC_V + (size_t)n * 192 + (size_t)D * 3;
            out[vb]     = v0 * S640;
            out[vb + 1] = v1 * S640;
            out[vb + 2] = aV2[j] * S640;
            float s0, s1; upk2(aV01s[j], s0, s1);
            g_xq2[(size_t)n * 64 + D] =
                make_float4(s0 * 0.125f, s1 * 0.125f, aV2s[j] * 0.125f,
                            accS2[j] * 0.125f);
        }
    }
}

// ============================================================================
// K4 v3: gather aggregation + output GEMMs with weights amortized over the
// 4 node-groups (threads 0-63: out_s x4; threads 64-255: out_v (d,comp) x4).
// ============================================================================
__global__ __launch_bounds__(256) void k_agg(
    const int* __restrict__ send, const float* __restrict__ eattr,
    float* __restrict__ out)
{
    __shared__ __align__(16) float sms[4][128];
    __shared__ __align__(16) float sv0[4][192];
    __shared__ __align__(16) float sv1[4][192];
    __shared__ __align__(16) float sv2[4][192];

    const int t = threadIdx.x;
    const int g = t >> 6, c = t & 63;
    const int nb = blockIdx.x * 4;
    const int n = nb + g;
    const int e0 = g_off[n], e1 = g_off[n + 1];

    float as0 = 0.f, as1 = 0.f;
    ull   av0_01 = 0ull, av1_01 = 0ull, av2_01 = 0ull;
    float av0_2 = 0.f, av1_2 = 0.f, av2_2 = 0.f;

    for (int p = e0; p < e1; p++) {
        const int e = g_eord[p];
        const int s = __ldg(send + e);
        const float4 ea = __ldg((const float4*)eattr + e);
        const float sh0 = ea.x, s1x = ea.y, s1y = ea.z, s1z = ea.w;
        const float* tp = g_tpw + (size_t)e * 320 + c;
        const float w0 = tp[0], w1 = tp[64], w2 = tp[128], w3 = tp[192], w4 = tp[256];
        const float4 xq = __ldg(g_xq2 + (size_t)s * 64 + c);
        const float xs = xq.w;

        as0 = fmaf(w0 * xs, sh0, as0);
        const float dt = xq.x * s1x + xq.y * s1y + xq.z * s1z;
        as1 = fmaf(w3, dt, as1);

        const float t1 = w1 * xs;
        av0_01 = ff2(pk2(t1, t1), pk2(s1x, s1y), av0_01);
        av0_2  = fmaf(t1, s1z, av0_2);

        const float w2sh = w2 * sh0;
        av1_01 = ff2(pk2(xq.x, xq.y), pk2(w2sh, w2sh), av1_01);
        av1_2  = fmaf(w2sh, xq.z, av1_2);

        const float cx = xq.y * s1z - xq.z * s1y;
        const float cy = xq.z * s1x - xq.x * s1z;
        const float cz = xq.x * s1y - xq.y * s1x;
        av2_01 = ff2(pk2(cx, cy), pk2(w4, w4), av2_01);
        av2_2  = fmaf(w4, cz, av2_2);
    }

    const float INV  = 0.3535533905932738f;            // 1/sqrt(8)
    const float INV3 = INV * 0.5773502691896258f;
    const float INV2 = INV * 0.7071067811865476f;
    sms[g][c]      = as0 * INV;
    sms[g][64 + c] = as1 * INV3;
    {
        float a, b;
        upk2(av0_01, a, b);
        sv0[g][c] = a * INV;  sv1[g][c] = b * INV;  sv2[g][c] = av0_2 * INV;
        upk2(av1_01, a, b);
        sv0[g][64 + c] = a * INV;  sv1[g][64 + c] = b * INV;
        sv2[g][64 + c] = av1_2 * INV;
        upk2(av2_01, a, b);
        sv0[g][128 + c] = a * INV2;  sv1[g][128 + c] = b * INV2;
        sv2[g][128 + c] = av2_2 * INV2;
    }
    __syncthreads();

    if (t < 64) {
        const int d = t;
        ull os[4] = {0ull, 0ull, 0ull, 0ull};
#pragma unroll 4
        for (int kp = 0; kp < 64; kp++) {
            const ull w = __ldg(g_wms2 + kp * 64 + d);
#pragma unroll
            for (int q = 0; q < 4; q++)
                os[q] = ff2(((const ull*)sms[q])[kp], w, os[q]);
        }
#pragma unroll
        for (int q = 0; q < 4; q++)
            out[(size_t)(nb + q) * 64 + d] = fold2(os[q]) * 0.08838834764831845f;
    } else {
        const int u = t - 64;
        const int d = u & 63;
        const int comp = u >> 6;  // 0,1,2
        const float* pl = (comp == 0) ? &sv0[0][0]
                        : (comp == 1) ? &sv1[0][0] : &sv2[0][0];
        ull ov[4] = {0ull, 0ull, 0ull, 0ull};
#pragma unroll 4
        for (int kp = 0; kp < 96; kp++) {
            const ull w = __ldg(g_wmv2 + kp * 64 + d);
#pragma unroll
            for (int q = 0; q < 4; q++)
                ov[q] = ff2(((const ull*)(pl + q * 192))[kp], w, ov[q]);
        }
        const float S192 = 0.07216878364870323f;  // 1/sqrt(192)
#pragma unroll
        for (int q = 0; q < 4; q++)
            out[O_OUT_V + (size_t)(nb + q) * 192 + (size_t)d * 3 + comp] =
                fold2(ov[q]) * S192;
    }
}

// ============================================================================
extern "C" void kernel_launch(void* const* d_in, const int* in_sizes, int n_in,
                              void* d_out, int out_size)
{
    const float* node_attrs = (const float*)d_in[0];
    const float* x_s        = (const float*)d_in[1];
    const float* x_v        = (const float*)d_in[2];
    const float* edge_attrs = (const float*)d_in[3];
    const float* edge_feats = (const float*)d_in[4];
    const int*   senders    = (const int*)d_in[5];
    const int*   receivers  = (const int*)d_in[6];
    const float* W_sc_s     = (const float*)d_in[7];
    const float* W_sc_v     = (const float*)d_in[8];
    const float* W_self_s   = (const float*)d_in[9];
    const float* W_self_v   = (const float*)d_in[10];
    const float* mlp_W0     = (const float*)d_in[11];
    const float* mlp_W1     = (const float*)d_in[12];
    const float* mlp_W2     = (const float*)d_in[13];
    const float* mlp_W3     = (const float*)d_in[14];
    const float* W_msg_s    = (const float*)d_in[15];
    const float* W_msg_v    = (const float*)d_in[16];
    float* out = (float*)d_out;

    const size_t mlp_smem  = (size_t)(512 + 2 * 64 * HPITCH) * sizeof(float); // 67584
    const size_t node_smem = (size_t)(640 * 16) * 8 + (size_t)(64 * 16) * 8;
    cudaFuncSetAttribute(k_mlp, cudaFuncAttributeMaxDynamicSharedMemorySize,
                         (int)mlp_smem);
    cudaFuncSetAttribute(k_node, cudaFuncAttributeMaxDynamicSharedMemorySize,
                         (int)node_smem);

    k_prep<<<160, 256>>>(W_sc_s, W_sc_v, W_self_s, W_self_v, W_msg_s, W_msg_v);
    k_prepx<<<NN * 64 / 256, 256>>>(x_s, x_v, receivers);
    k_mlp<<<EE / 128, 128, mlp_smem>>>(edge_feats, mlp_W0, mlp_W1, mlp_W2, mlp_W3);
    k_node<<<dim3(128, 4), 256, node_smem>>>(node_attrs, out);   // profiled (#4)
    k_scan_a<<<32, 1024>>>();
    k_scan_b<<<1, 32>>>();
    k_scan_c<<<128, 256>>>();
    k_fill<<<EE / 256, 256>>>(receivers);
    k_sort<<<NN / 128, 128>>>();
    k_agg<<<NN / 4, 256>>>(senders, edge_attrs, out);
}